// round 2
// baseline (speedup 1.0000x reference)
#include <cuda_runtime.h>

#define TLEN 4096
#define BROWS 2048
#define SHIFTW 10
#define NSHIFT 21
#define THREADS 256
#define QUADS_PER_THREAD (TLEN / (THREADS * 4))

__device__ float g_row_mse[BROWS];

__global__ __launch_bounds__(THREADS) void shift_loss_row_kernel(
    const float* __restrict__ x, const float* __restrict__ y)
{
    const int row = blockIdx.x;
    const float* __restrict__ xr = x + (size_t)row * TLEN;
    const float* __restrict__ yr = y + (size_t)row * TLEN;
    const int tid = threadIdx.x;

    __shared__ float red[THREADS / 32][25];
    __shared__ float tot[25];
    __shared__ float corr_sh[NSHIFT];
    __shared__ float mse_sh[NSHIFT];

    float acc[NSHIFT];
#pragma unroll
    for (int s = 0; s < NSHIFT; ++s) acc[s] = 0.f;
    float sx = 0.f, sxx = 0.f, sy = 0.f, syy = 0.f;

#pragma unroll
    for (int it = 0; it < QUADS_PER_THREAD; ++it) {
        const int t0 = (it * THREADS + tid) * 4;

        // x quad (coalesced LDG.128)
        float4 xv = *reinterpret_cast<const float4*>(xr + t0);
        float xk[4] = {xv.x, xv.y, xv.z, xv.w};

        // y window [t0-12, t0+15], zero-padded outside the row.
        // 7 coalesced float4 loads; overlap across threads hits L1.
        float w[28];
#pragma unroll
        for (int j = 0; j < 7; ++j) {
            const int yb = t0 - 12 + 4 * j;
            if (yb >= 0 && yb + 4 <= TLEN) {
                float4 v = *reinterpret_cast<const float4*>(yr + yb);
                w[4 * j + 0] = v.x; w[4 * j + 1] = v.y;
                w[4 * j + 2] = v.z; w[4 * j + 3] = v.w;
            } else {
#pragma unroll
                for (int k = 0; k < 4; ++k) {
                    const int yi = yb + k;
                    w[4 * j + k] = (yi >= 0 && yi < TLEN) ? yr[yi] : 0.f;
                }
            }
        }

#pragma unroll
        for (int k = 0; k < 4; ++k) { sx += xk[k]; sxx += xk[k] * xk[k]; }
#pragma unroll
        for (int k = 0; k < 4; ++k) {
            const float yv = w[12 + k];           // own quad: y[t0+k], always in-bounds
            sy += yv; syy += yv * yv;
        }

        // acc[s] += x[t0+k] * y[t0+k+(s-10)]  ->  w index = k + s + 2
#pragma unroll
        for (int s = 0; s < NSHIFT; ++s) {
#pragma unroll
            for (int k = 0; k < 4; ++k)
                acc[s] += xk[k] * w[k + s + 2];
        }
    }

    // ---- block reduction of 25 partials ----
    float vals[25];
    vals[0] = sx; vals[1] = sxx; vals[2] = sy; vals[3] = syy;
#pragma unroll
    for (int s = 0; s < NSHIFT; ++s) vals[4 + s] = acc[s];

#pragma unroll
    for (int i = 0; i < 25; ++i) {
#pragma unroll
        for (int o = 16; o > 0; o >>= 1)
            vals[i] += __shfl_down_sync(0xffffffffu, vals[i], o);
    }
    const int wid = tid >> 5, lane = tid & 31;
    if (lane == 0) {
#pragma unroll
        for (int i = 0; i < 25; ++i) red[wid][i] = vals[i];
    }
    __syncthreads();
    if (tid < 25) {
        float t = 0.f;
#pragma unroll
        for (int wb = 0; wb < THREADS / 32; ++wb) t += red[wb][tid];
        tot[tid] = t;
    }
    __syncthreads();

    // ---- 21 threads: per-shift trimmed Pearson + MSE ----
    if (tid < NSHIFT) {
        const int sh = tid - SHIFTW;
        float Sx = tot[0], Sxx = tot[1], Sy = tot[2], Syy = tot[3];
        const int m = sh < 0 ? -sh : sh;
        const float n = (float)(TLEN - m);
        if (sh > 0) {
            for (int i = 0; i < sh; ++i) {
                const float xv = xr[TLEN - 1 - i]; Sx -= xv; Sxx -= xv * xv;
                const float yv = yr[i];            Sy -= yv; Syy -= yv * yv;
            }
        } else if (sh < 0) {
            for (int i = 0; i < m; ++i) {
                const float xv = xr[i];            Sx -= xv; Sxx -= xv * xv;
                const float yv = yr[TLEN - 1 - i]; Sy -= yv; Syy -= yv * yv;
            }
        }
        const float Sxy = tot[4 + tid];
        const float inv_n = 1.f / n;
        const float cov = Sxy - Sx * Sy * inv_n;
        const float vx  = Sxx - Sx * Sx * inv_n;
        const float vy  = Syy - Sy * Sy * inv_n;
        corr_sh[tid] = cov * rsqrtf(vx * vy);
        mse_sh[tid]  = (Sxx + Syy - 2.f * Sxy) * inv_n;
    }
    __syncthreads();

    if (tid == 0) {
        float best = corr_sh[0];
        int bi = 0;
#pragma unroll
        for (int s = 1; s < NSHIFT; ++s) {
            if (corr_sh[s] > best) { best = corr_sh[s]; bi = s; }  // first-max tie-break
        }
        g_row_mse[row] = mse_sh[bi];
    }
}

__global__ __launch_bounds__(256) void shift_loss_final_kernel(float* __restrict__ out)
{
    __shared__ float sh[8];
    float s = 0.f;
    for (int i = threadIdx.x; i < BROWS; i += 256) s += g_row_mse[i];
#pragma unroll
    for (int o = 16; o > 0; o >>= 1) s += __shfl_down_sync(0xffffffffu, s, o);
    if ((threadIdx.x & 31) == 0) sh[threadIdx.x >> 5] = s;
    __syncthreads();
    if (threadIdx.x == 0) {
        float t = 0.f;
#pragma unroll
        for (int w = 0; w < 8; ++w) t += sh[w];
        out[0] = t / (float)BROWS;
    }
}

extern "C" void kernel_launch(void* const* d_in, const int* in_sizes, int n_in,
                              void* d_out, int out_size)
{
    const float* x = (const float*)d_in[0];
    const float* y = (const float*)d_in[1];
    shift_loss_row_kernel<<<BROWS, THREADS>>>(x, y);
    shift_loss_final_kernel<<<1, 256>>>((float*)d_out);
}